// round 11
// baseline (speedup 1.0000x reference)
#include <cuda_runtime.h>
#include <cstdint>

#define NN 4
#define PP 128
#define HH 64
#define UU 64
#define BB 15
#define FAVG 49.0f
#define NPG 64   // p-groups for colsum partials (2 p's each)

// ---------------- device scratch ----------------
__device__ float g_rows[NN*HH*PP];         // sum_q x / npart   [n][h][p]
__device__ float g_diag[NN*HH*PP];         // x[p,p]            [n][h][p]
__device__ float g_cpart[NPG*NN*PP*HH];    // partial colsums   [pg][n][q][h]
__device__ float g_Fq[NN*PP*UU];           // q-field (includes bias)
__device__ float g_Fp[NN*PP*UU];           // p-field (includes scalar terms)
__device__ float g_Fd[NN*PP*UU];           // diag field (diag_bias + scalar terms)

// ---------------- f32x2 helpers ----------------
#define FMA2(d, a, b) asm("fma.rn.f32x2 %0, %1, %2, %0;" : "+l"(d) : "l"(a), "l"(b))
#define PK2(d, f) do { unsigned int _t = __float_as_uint(f); \
    asm("mov.b64 %0, {%1, %1};" : "=l"(d) : "r"(_t)); } while (0)
#define UPK2(lo, hi, v) asm("mov.b64 {%0, %1}, %2;" : "=f"(lo), "=f"(hi) : "l"(v))

// ---------------- pass 1 (fused): single x read -> rows, diag, colsum partials ----------------
__global__ void __launch_bounds__(256)
fuse_kernel(const float* __restrict__ x, const float* __restrict__ npart) {
    const int pg = blockIdx.x;         // p-group (2 p's)
    const int n  = blockIdx.y;
    const int p0 = pg * 2;
    const int t  = threadIdx.x;
    const int h4 = t & 15;
    const int qg = t >> 4;

    __shared__ float4 spart[16][2][16];

    const float4* x4 = (const float4*)x;
    const float inv = 1.0f / npart[n];

    float4 col[8];
    #pragma unroll
    for (int j = 0; j < 8; ++j) col[j] = make_float4(0.f, 0.f, 0.f, 0.f);

    #pragma unroll
    for (int p = 0; p < 2; ++p) {
        float4 rp = make_float4(0.f, 0.f, 0.f, 0.f);
        const size_t base = ((size_t)(n * PP + p0 + p)) * PP * 16;
        #pragma unroll
        for (int j = 0; j < 8; ++j) {
            const int q = qg + j * 16;
            const float4 v = x4[base + q * 16 + h4];
            col[j].x += v.x; col[j].y += v.y; col[j].z += v.z; col[j].w += v.w;
            rp.x += v.x; rp.y += v.y; rp.z += v.z; rp.w += v.w;
        }
        spart[qg][p][h4] = rp;
    }
    {
        float4* cp = (float4*)g_cpart + ((size_t)(pg * NN + n)) * PP * 16;
        #pragma unroll
        for (int j = 0; j < 8; ++j)
            cp[(qg + j * 16) * 16 + h4] = col[j];
    }
    __syncthreads();
    if (t < 32) {
        const int p   = t >> 4;
        const int hh4 = t & 15;
        float4 r = spart[0][p][hh4];
        #pragma unroll
        for (int g = 1; g < 16; ++g) {
            const float4 v = spart[g][p][hh4];
            r.x += v.x; r.y += v.y; r.z += v.z; r.w += v.w;
        }
        const int P = p0 + p;
        const int gb = (n * HH + hh4 * 4) * PP + P;
        g_rows[gb + 0*PP] = r.x * inv;
        g_rows[gb + 1*PP] = r.y * inv;
        g_rows[gb + 2*PP] = r.z * inv;
        g_rows[gb + 3*PP] = r.w * inv;
        const float4 d = x4[(((size_t)(n * PP + P)) * PP + P) * 16 + hh4];
        g_diag[gb + 0*PP] = d.x;
        g_diag[gb + 1*PP] = d.y;
        g_diag[gb + 2*PP] = d.z;
        g_diag[gb + 3*PP] = d.w;
    }
}

// ---------------- pass 2 (fused): scalars + coefficients + field GEMMs ----------------
__global__ void __launch_bounds__(256)
pro_kernel(const float* __restrict__ npart,
           const float* __restrict__ alpha0,
           const float* __restrict__ c00,
           const float* __restrict__ c01,
           const float* __restrict__ c10,
           const float* __restrict__ c11,
           const float* __restrict__ bias,
           const float* __restrict__ dbias) {
    const int n  = blockIdx.y;
    const int i0 = blockIdx.x * 4;
    const int tid = threadIdx.x;

    __shared__ float sRR[HH * UU];
    __shared__ float sD[HH][4], sC[HH][4], sR[HH][4];
    __shared__ float sSD[HH], sSA[HH];
    __shared__ float sM[HH][10];
    __shared__ float sA[HH][16];

    const float np  = npart[n];
    const float inv = 1.0f / np;

    #pragma unroll
    for (int it = 0; it < 16; ++it) {
        const int idx = tid + it * 256;
        sRR[idx] = c10[idx] * c11[idx];
    }
    {
        const int hh = tid >> 2;
        const int ii = tid & 3;
        const int gi = (n * HH + hh) * PP + i0 + ii;
        sD[hh][ii] = g_diag[gi];
        sR[hh][ii] = g_rows[gi];
    }
    {
        const int hh = tid & 63;
        const int ii = tid >> 6;
        const float* cp = g_cpart + ((size_t)n * PP + i0 + ii) * HH + hh;
        float s = 0.0f;
        #pragma unroll 16
        for (int g = 0; g < NPG; ++g)
            s += cp[(size_t)g * (NN * PP * HH)];
        sC[hh][ii] = s * inv;
    }
    {
        const int w = tid >> 5, lane = tid & 31;
        #pragma unroll
        for (int j = 0; j < 8; ++j) {
            const int h = w * 8 + j;
            const int base = (n * HH + h) * PP;
            float d = g_diag[base + lane] + g_diag[base + lane + 32]
                    + g_diag[base + lane + 64] + g_diag[base + lane + 96];
            float r = g_rows[base + lane] + g_rows[base + lane + 32]
                    + g_rows[base + lane + 64] + g_rows[base + lane + 96];
            #pragma unroll
            for (int o = 16; o > 0; o >>= 1) {
                d += __shfl_down_sync(0xffffffffu, d, o);
                r += __shfl_down_sync(0xffffffffu, r, o);
            }
            if (lane == 0) { sSD[h] = d * inv; sSA[h] = r * inv; }
        }
    }
    {
        const float ratio = np / FAVG;
        for (int idx = tid; idx < HH * 10; idx += 256)
            sM[idx / 10][idx % 10] = powf(ratio, alpha0[idx]);
    }
    for (int idx = tid; idx < HH * BB; idx += 256)
        sA[idx / BB][idx % BB] = c00[idx];
    __syncthreads();

    const int u  = tid & 63;
    const int ii = tid >> 6;

    float cb[BB];
    #pragma unroll
    for (int b = 2; b < BB; ++b) cb[b] = c01[b * UU + u];

    float aq = 0.0f, ap = 0.0f, ad = 0.0f, vp = 0.0f, vd = 0.0f;

    #pragma unroll 4
    for (int h = 0; h < HH; ++h) {
        const float r = sRR[h * UU + u];
        const float* a = sA[h];
        const float* m = sM[h];
        const float d  = sD[h][ii];
        const float cl = sC[h][ii];
        const float rw = sR[h][ii];
        aq += (a[2]  * cb[2]  * r)        * d
            + (a[5]  * cb[5]  * r * m[0]) * cl
            + (a[6]  * cb[6]  * r * m[1]) * rw;
        ap += (a[3]  * cb[3]  * r)        * d
            + (a[8]  * cb[8]  * r * m[3]) * cl
            + (a[9]  * cb[9]  * r * m[4]) * rw;
        ad += (a[4]  * cb[4]  * r)        * d
            + (a[12] * cb[12] * r * m[7]) * cl
            + (a[11] * cb[11] * r * m[6]) * rw;
        vp += (a[7]  * cb[7]  * r * m[2]) * sSD[h]
            + (a[13] * cb[13] * r * m[8]) * sSA[h];
        vd += (a[10] * cb[10] * r * m[5]) * sSD[h]
            + (a[14] * cb[14] * r * m[9]) * sSA[h];
    }

    const int i = i0 + ii;
    g_Fq[(n * PP + i) * UU + u] = aq + bias[u];
    g_Fp[(n * PP + i) * UU + u] = ap + vp;
    g_Fd[(n * PP + i) * UU + u] = ad + vd + dbias[u];
}

// ---------------- main: dual skinny GEMM, two passes over ONE X buffer ----------------
// smem = 32KB X + 32KB C + 0.5KB -> 64.5KB -> 3 blocks/SM
constexpr int SMEM_FLOATS = 64 * 128 + 2 * 64 * 64 + 128;

__global__ void __launch_bounds__(256, 3)
main_kernel(const float* __restrict__ x,
            const unsigned int* __restrict__ mask,
            const float* __restrict__ c00,
            const float* __restrict__ c01,
            const float* __restrict__ c10,
            const float* __restrict__ c11,
            float* __restrict__ out) {
    extern __shared__ float sm[];
    float* sX  = sm;                         // [k=64][q=128] XOR-swizzled (Xd then Xt)
    float* sC0 = sX + 64 * 128;              // [k=64][u=64]
    float* sC1 = sC0 + 64 * 64;
    float* sFp = sC1 + 64 * 64;              // [64]
    float* sFd = sFp + 64;                   // [64]

    const int bid = blockIdx.x;
    const int tid = threadIdx.x;

    // C0/C1 once per block (tile-independent)
    #pragma unroll
    for (int it = 0; it < 16; ++it) {
        const int idx = tid + it * 256;      // h*64+u
        const int h = idx >> 6;
        const int uu = idx & 63;
        const float r = c10[idx] * c11[idx];
        sC0[idx] = c00[h * BB + 0] * c01[uu] * r;
        sC1[idx] = c00[h * BB + 1] * c01[UU + uu] * r;
    }

    const int tx = tid & 15;
    const int ty = tid >> 4;
    const int u0 = tx << 2;
    const int q0 = ty << 3;

    #pragma unroll 1
    for (int tt = 0; tt < 2; ++tt) {
        const int tile = bid * 2 + tt;
        const int p = tile & 127;
        const int n = tile >> 7;
        if (tt > 0) __syncthreads();         // epilogue/GEMM2 done before sX overwrite

        // ---- pass A: direct tile x[n,p,q,h] -> sX[h][swz(q)] ----
        const float4* xrow4 = (const float4*)(x + ((size_t)(n * PP + p)) * PP * HH);
        #pragma unroll
        for (int it = 0; it < 8; ++it) {
            const int idx4 = tid + it * 256;
            const float4 v = xrow4[idx4];
            const int q  = idx4 >> 4;
            const int h0 = (idx4 & 15) << 2;
            const int qs = q ^ ((idx4 & 7) << 3);
            sX[(h0 + 0) * 128 + qs] = v.x;
            sX[(h0 + 1) * 128 + qs] = v.y;
            sX[(h0 + 2) * 128 + qs] = v.z;
            sX[(h0 + 3) * 128 + qs] = v.w;
        }
        if (tid < 64) {
            sFp[tid] = g_Fp[(n * PP + p) * UU + tid];
            sFd[tid] = g_Fd[(n * PP + p) * UU + tid];
        }
        __syncthreads();

        unsigned long long acc[4][4];
        #pragma unroll
        for (int i = 0; i < 4; ++i)
            #pragma unroll
            for (int j = 0; j < 4; ++j) acc[i][j] = 0ULL;

        #pragma unroll 8
        for (int k = 0; k < 64; ++k) {
            const float4 b0 = *(const float4*)(sC0 + k * 64 + u0);
            unsigned long long bb0[4];
            PK2(bb0[0], b0.x); PK2(bb0[1], b0.y); PK2(bb0[2], b0.z); PK2(bb0[3], b0.w);
            const int kq = k * 128 + (q0 ^ (((k >> 2) & 7) << 3));
            const ulonglong2 a01 = *(const ulonglong2*)(sX + kq);
            const ulonglong2 a23 = *(const ulonglong2*)(sX + kq + 4);
            const unsigned long long av[4] = {a01.x, a01.y, a23.x, a23.y};
            #pragma unroll
            for (int qp = 0; qp < 4; ++qp)
                #pragma unroll
                for (int j = 0; j < 4; ++j)
                    FMA2(acc[qp][j], av[qp], bb0[j]);
        }
        __syncthreads();

        // ---- pass B: transposed tile x[n,r,p,h] -> sX[h][swz(r)] ----
        {
            const int h0 = (tid & 15) << 2;
            const int sw = (tid & 7) << 3;
            #pragma unroll
            for (int it = 0; it < 8; ++it) {
                const int r = (tid >> 4) + it * 16;
                const float4 v = *(const float4*)(x + (((size_t)(n * PP + r)) * PP + p) * HH + h0);
                const int rs = r ^ sw;
                sX[(h0 + 0) * 128 + rs] = v.x;
                sX[(h0 + 1) * 128 + rs] = v.y;
                sX[(h0 + 2) * 128 + rs] = v.z;
                sX[(h0 + 3) * 128 + rs] = v.w;
            }
        }
        __syncthreads();

        #pragma unroll 8
        for (int k = 0; k < 64; ++k) {
            const float4 b1 = *(const float4*)(sC1 + k * 64 + u0);
            unsigned long long bb1[4];
            PK2(bb1[0], b1.x); PK2(bb1[1], b1.y); PK2(bb1[2], b1.z); PK2(bb1[3], b1.w);
            const int kq = k * 128 + (q0 ^ (((k >> 2) & 7) << 3));
            const ulonglong2 t01 = *(const ulonglong2*)(sX + kq);
            const ulonglong2 t23 = *(const ulonglong2*)(sX + kq + 4);
            const unsigned long long tv[4] = {t01.x, t01.y, t23.x, t23.y};
            #pragma unroll
            for (int qp = 0; qp < 4; ++qp)
                #pragma unroll
                for (int j = 0; j < 4; ++j)
                    FMA2(acc[qp][j], tv[qp], bb1[j]);
        }

        // ---- epilogue ----
        const float4 fp4 = *(const float4*)(sFp + u0);
        const float4 fd4 = *(const float4*)(sFd + u0);
        const unsigned int* em = mask + (size_t)(n * PP + p) * PP;
        #pragma unroll
        for (int qp = 0; qp < 4; ++qp) {
            float lo[4], hi[4];
            #pragma unroll
            for (int j = 0; j < 4; ++j) UPK2(lo[j], hi[j], acc[qp][j]);
            #pragma unroll
            for (int half = 0; half < 2; ++half) {
                const int q = q0 + 2 * qp + half;
                const float* v = half ? hi : lo;
                const float4 fq = *(const float4*)(g_Fq + ((size_t)(n * PP + q)) * UU + u0);
                const float msk = (em[q] != 0u) ? 1.0f : 0.0f;
                const float de = (q == p) ? 1.0f : 0.0f;
                float4 o;
                o.x = (v[0] + fq.x + fp4.x + de * fd4.x) * msk;
                o.y = (v[1] + fq.y + fp4.y + de * fd4.y) * msk;
                o.z = (v[2] + fq.z + fp4.z + de * fd4.z) * msk;
                o.w = (v[3] + fq.w + fp4.w + de * fd4.w) * msk;
                *(float4*)(out + (((size_t)(n * PP + p)) * PP + q) * UU + u0) = o;
            }
        }
    }
}

// ---------------- launch ----------------
extern "C" void kernel_launch(void* const* d_in, const int* in_sizes, int n_in,
                              void* d_out, int out_size) {
    (void)in_sizes; (void)n_in; (void)out_size;
    const float*        x      = (const float*)d_in[0];
    const unsigned int* mask   = (const unsigned int*)d_in[1];
    const float*        npart  = (const float*)d_in[2];
    const float*        alpha0 = (const float*)d_in[3];
    const float*        c00    = (const float*)d_in[4];
    const float*        c01    = (const float*)d_in[5];
    const float*        c10    = (const float*)d_in[6];
    const float*        c11    = (const float*)d_in[7];
    const float*        bias   = (const float*)d_in[8];
    const float*        dbias  = (const float*)d_in[9];
    float* out = (float*)d_out;

    fuse_kernel<<<dim3(NPG, NN), 256>>>(x, npart);
    pro_kernel<<<dim3(32, NN), 256>>>(npart, alpha0, c00, c01, c10, c11, bias, dbias);

    cudaFuncSetAttribute(main_kernel, cudaFuncAttributeMaxDynamicSharedMemorySize,
                         SMEM_FLOATS * 4);
    main_kernel<<<256, 256, SMEM_FLOATS * 4>>>(x, mask, c00, c01, c10, c11, out);
}

// round 12
// speedup vs baseline: 1.1429x; 1.1429x over previous
#include <cuda_runtime.h>
#include <cstdint>

#define NN 4
#define PP 128
#define HH 64
#define UU 64
#define BB 15
#define FAVG 49.0f
#define NPG 32   // p-groups for colsum partials (4 p's each)

// ---------------- device scratch ----------------
__device__ float g_rows[NN*HH*PP];         // sum_q x / npart   [n][h][p]
__device__ float g_diag[NN*HH*PP];         // x[p,p]            [n][h][p]
__device__ float g_cpart[NPG*NN*PP*HH];    // partial colsums   [pg][n][q][h]
__device__ float g_Fq[NN*PP*UU];           // q-field (includes bias)
__device__ float g_Fp[NN*PP*UU];           // p-field (includes scalar terms)
__device__ float g_Fd[NN*PP*UU];           // diag field (diag_bias + scalar terms)

// ---------------- pass 1 (fused): single x read -> rows, diag, colsum partials ----------------
__global__ void __launch_bounds__(256)
fuse_kernel(const float* __restrict__ x, const float* __restrict__ npart) {
    const int pg = blockIdx.x;         // p-group (4 p's)
    const int n  = blockIdx.y;
    const int p0 = pg * 4;
    const int t  = threadIdx.x;
    const int h4 = t & 15;
    const int qg = t >> 4;

    __shared__ float4 spart[16][4][16];

    const float4* x4 = (const float4*)x;
    const float inv = 1.0f / npart[n];

    float4 col[8];
    #pragma unroll
    for (int j = 0; j < 8; ++j) col[j] = make_float4(0.f, 0.f, 0.f, 0.f);

    #pragma unroll
    for (int p = 0; p < 4; ++p) {
        float4 rp = make_float4(0.f, 0.f, 0.f, 0.f);
        const size_t base = ((size_t)(n * PP + p0 + p)) * PP * 16;
        #pragma unroll
        for (int j = 0; j < 8; ++j) {
            const int q = qg + j * 16;
            const float4 v = x4[base + q * 16 + h4];
            col[j].x += v.x; col[j].y += v.y; col[j].z += v.z; col[j].w += v.w;
            rp.x += v.x; rp.y += v.y; rp.z += v.z; rp.w += v.w;
        }
        spart[qg][p][h4] = rp;
    }
    {
        float4* cp = (float4*)g_cpart + ((size_t)(pg * NN + n)) * PP * 16;
        #pragma unroll
        for (int j = 0; j < 8; ++j)
            cp[(qg + j * 16) * 16 + h4] = col[j];
    }
    __syncthreads();
    if (t < 64) {
        const int p   = t >> 4;
        const int hh4 = t & 15;
        float4 r = spart[0][p][hh4];
        #pragma unroll
        for (int g = 1; g < 16; ++g) {
            const float4 v = spart[g][p][hh4];
            r.x += v.x; r.y += v.y; r.z += v.z; r.w += v.w;
        }
        const int P = p0 + p;
        const int gb = (n * HH + hh4 * 4) * PP + P;
        g_rows[gb + 0*PP] = r.x * inv;
        g_rows[gb + 1*PP] = r.y * inv;
        g_rows[gb + 2*PP] = r.z * inv;
        g_rows[gb + 3*PP] = r.w * inv;
        const float4 d = x4[(((size_t)(n * PP + P)) * PP + P) * 16 + hh4];
        g_diag[gb + 0*PP] = d.x;
        g_diag[gb + 1*PP] = d.y;
        g_diag[gb + 2*PP] = d.z;
        g_diag[gb + 3*PP] = d.w;
    }
}

// ---------------- pass 2 (fused): scalars + coefficients + field GEMMs ----------------
__global__ void __launch_bounds__(256)
pro_kernel(const float* __restrict__ npart,
           const float* __restrict__ alpha0,
           const float* __restrict__ c00,
           const float* __restrict__ c01,
           const float* __restrict__ c10,
           const float* __restrict__ c11,
           const float* __restrict__ bias,
           const float* __restrict__ dbias) {
    const int n  = blockIdx.y;
    const int i0 = blockIdx.x * 4;
    const int tid = threadIdx.x;

    __shared__ float sRR[HH * UU];
    __shared__ float sD[HH][4], sC[HH][4], sR[HH][4];
    __shared__ float sSD[HH], sSA[HH];
    __shared__ float sM[HH][10];
    __shared__ float sA[HH][16];

    const float np  = npart[n];
    const float inv = 1.0f / np;

    #pragma unroll
    for (int it = 0; it < 16; ++it) {
        const int idx = tid + it * 256;
        sRR[idx] = c10[idx] * c11[idx];
    }
    {
        const int hh = tid >> 2;
        const int ii = tid & 3;
        const int gi = (n * HH + hh) * PP + i0 + ii;
        sD[hh][ii] = g_diag[gi];
        sR[hh][ii] = g_rows[gi];
    }
    {
        const int hh = tid & 63;
        const int ii = tid >> 6;
        const float* cp = g_cpart + ((size_t)n * PP + i0 + ii) * HH + hh;
        float s = 0.0f;
        #pragma unroll 8
        for (int g = 0; g < NPG; ++g)
            s += cp[(size_t)g * (NN * PP * HH)];
        sC[hh][ii] = s * inv;
    }
    {
        const int w = tid >> 5, lane = tid & 31;
        #pragma unroll
        for (int j = 0; j < 8; ++j) {
            const int h = w * 8 + j;
            const int base = (n * HH + h) * PP;
            float d = g_diag[base + lane] + g_diag[base + lane + 32]
                    + g_diag[base + lane + 64] + g_diag[base + lane + 96];
            float r = g_rows[base + lane] + g_rows[base + lane + 32]
                    + g_rows[base + lane + 64] + g_rows[base + lane + 96];
            #pragma unroll
            for (int o = 16; o > 0; o >>= 1) {
                d += __shfl_down_sync(0xffffffffu, d, o);
                r += __shfl_down_sync(0xffffffffu, r, o);
            }
            if (lane == 0) { sSD[h] = d * inv; sSA[h] = r * inv; }
        }
    }
    {
        const float ratio = np / FAVG;
        for (int idx = tid; idx < HH * 10; idx += 256)
            sM[idx / 10][idx % 10] = powf(ratio, alpha0[idx]);
    }
    for (int idx = tid; idx < HH * BB; idx += 256)
        sA[idx / BB][idx % BB] = c00[idx];
    __syncthreads();

    const int u  = tid & 63;
    const int ii = tid >> 6;

    float cb[BB];
    #pragma unroll
    for (int b = 2; b < BB; ++b) cb[b] = c01[b * UU + u];

    float aq = 0.0f, ap = 0.0f, ad = 0.0f, vp = 0.0f, vd = 0.0f;

    #pragma unroll 4
    for (int h = 0; h < HH; ++h) {
        const float r = sRR[h * UU + u];
        const float* a = sA[h];
        const float* m = sM[h];
        const float d  = sD[h][ii];
        const float cl = sC[h][ii];
        const float rw = sR[h][ii];
        aq += (a[2]  * cb[2]  * r)        * d
            + (a[5]  * cb[5]  * r * m[0]) * cl
            + (a[6]  * cb[6]  * r * m[1]) * rw;
        ap += (a[3]  * cb[3]  * r)        * d
            + (a[8]  * cb[8]  * r * m[3]) * cl
            + (a[9]  * cb[9]  * r * m[4]) * rw;
        ad += (a[4]  * cb[4]  * r)        * d
            + (a[12] * cb[12] * r * m[7]) * cl
            + (a[11] * cb[11] * r * m[6]) * rw;
        vp += (a[7]  * cb[7]  * r * m[2]) * sSD[h]
            + (a[13] * cb[13] * r * m[8]) * sSA[h];
        vd += (a[10] * cb[10] * r * m[5]) * sSD[h]
            + (a[14] * cb[14] * r * m[9]) * sSA[h];
    }

    const int i = i0 + ii;
    g_Fq[(n * PP + i) * UU + u] = aq + bias[u];
    g_Fp[(n * PP + i) * UU + u] = ap + vp;
    g_Fd[(n * PP + i) * UU + u] = ad + vd + dbias[u];
}

// ---------------- main: tf32 tensor-core GEMM with error compensation ----------------
// out_gemm = Xr·Cr + Xe·Cr + Xr·Ce   (Xe·Ce dropped, ~2^-22)
#define SA_STRIDE 68   // [q=128][k=64] pad -> conflict-free A frags
#define SB_STRIDE 72   // [k=64][u=64] pad -> conflict-free B frags
constexpr int SMEM_FLOATS = 2 * 128 * SA_STRIDE + 2 * 64 * SB_STRIDE + 128;

#define CVT_TF32(r, f) asm("cvt.rna.tf32.f32 %0, %1;" : "=r"(r) : "f"(f))

#define MMA_TF32(d, a, b0_, b1_) \
    asm volatile("mma.sync.aligned.m16n8k8.row.col.f32.tf32.tf32.f32 " \
        "{%0,%1,%2,%3},{%4,%5,%6,%7},{%8,%9},{%0,%1,%2,%3};" \
        : "+f"(d[0]), "+f"(d[1]), "+f"(d[2]), "+f"(d[3]) \
        : "r"(a[0]), "r"(a[1]), "r"(a[2]), "r"(a[3]), "r"(b0_), "r"(b1_))

__global__ void __launch_bounds__(256, 2)
main_kernel(const float* __restrict__ x,
            const unsigned int* __restrict__ mask,
            const float* __restrict__ c00,
            const float* __restrict__ c01,
            const float* __restrict__ c10,
            const float* __restrict__ c11,
            float* __restrict__ out) {
    extern __shared__ float sm[];
    float* sXr = sm;                          // [128][68]
    float* sXe = sXr + 128 * SA_STRIDE;       // [128][68]
    float* sBr = sXe + 128 * SA_STRIDE;       // [64][72]
    float* sBe = sBr + 64 * SB_STRIDE;        // [64][72]
    float* sFp = sBe + 64 * SB_STRIDE;        // [64]
    float* sFd = sFp + 64;                    // [64]

    const int p = blockIdx.x;
    const int n = blockIdx.y;
    const int tid = threadIdx.x;
    const int lane = tid & 31;
    const int w = tid >> 5;
    const int mw = w & 3;                     // 4 m-warps
    const int nw = w >> 2;                    // 2 n-warps
    const int g = lane >> 2;                  // 0..7
    const int c = lane & 3;                   // 0..3
    const int m0 = mw * 32;
    const int n0 = nw * 32;

    if (tid < 64) {
        sFp[tid] = g_Fp[(n * PP + p) * UU + tid];
        sFd[tid] = g_Fd[(n * PP + p) * UU + tid];
    }

    float acc[2][4][4];
    #pragma unroll
    for (int mt = 0; mt < 2; ++mt)
        #pragma unroll
        for (int nt = 0; nt < 4; ++nt)
            #pragma unroll
            for (int j = 0; j < 4; ++j) acc[mt][nt][j] = 0.0f;

    #pragma unroll 1
    for (int pass = 0; pass < 2; ++pass) {
        if (pass > 0) __syncthreads();   // all warps done with previous tiles

        // ---- fill X (direct for pass 0, transposed for pass 1), split tf32 ----
        if (pass == 0) {
            const float4* xrow4 = (const float4*)(x + ((size_t)(n * PP + p)) * PP * HH);
            #pragma unroll
            for (int it = 0; it < 8; ++it) {
                const int idx4 = tid + it * 256;
                const float4 v = xrow4[idx4];
                const int q  = idx4 >> 4;
                const int h0 = (idx4 & 15) << 2;
                const float f[4] = {v.x, v.y, v.z, v.w};
                #pragma unroll
                for (int j = 0; j < 4; ++j) {
                    unsigned int r; CVT_TF32(r, f[j]);
                    const float rf = __uint_as_float(r);
                    sXr[q * SA_STRIDE + h0 + j] = rf;
                    sXe[q * SA_STRIDE + h0 + j] = f[j] - rf;
                }
            }
        } else {
            const int h0 = (tid & 15) << 2;
            #pragma unroll
            for (int it = 0; it < 8; ++it) {
                const int r = (tid >> 4) + it * 16;
                const float4 v = *(const float4*)(x + (((size_t)(n * PP + r)) * PP + p) * HH + h0);
                const float f[4] = {v.x, v.y, v.z, v.w};
                #pragma unroll
                for (int j = 0; j < 4; ++j) {
                    unsigned int rr; CVT_TF32(rr, f[j]);
                    const float rf = __uint_as_float(rr);
                    sXr[r * SA_STRIDE + h0 + j] = rf;
                    sXe[r * SA_STRIDE + h0 + j] = f[j] - rf;
                }
            }
        }
        // ---- fill B = C_pass (k x u), split tf32 ----
        {
            const int bsel = pass;   // basis 0 -> direct, 1 -> transposed
            #pragma unroll
            for (int it = 0; it < 16; ++it) {
                const int idx = tid + it * 256;    // k*64+u
                const int k = idx >> 6;
                const int u = idx & 63;
                const float val = c00[k * BB + bsel] * c01[bsel * UU + u]
                                * c10[idx] * c11[idx];
                unsigned int r; CVT_TF32(r, val);
                const float rf = __uint_as_float(r);
                sBr[k * SB_STRIDE + u] = rf;
                sBe[k * SB_STRIDE + u] = val - rf;
            }
        }
        __syncthreads();

        // ---- tensor-core GEMM: 8 k-steps, 2 m-tiles x 4 n-tiles per warp ----
        #pragma unroll
        for (int kk = 0; kk < 8; ++kk) {
            const int ka = kk * 8 + c;
            unsigned int ar[2][4], ae[2][4];
            #pragma unroll
            for (int mt = 0; mt < 2; ++mt) {
                const int row = m0 + 16 * mt + g;
                ar[mt][0] = __float_as_uint(sXr[row * SA_STRIDE + ka]);
                ar[mt][1] = __float_as_uint(sXr[(row + 8) * SA_STRIDE + ka]);
                ar[mt][2] = __float_as_uint(sXr[row * SA_STRIDE + ka + 4]);
                ar[mt][3] = __float_as_uint(sXr[(row + 8) * SA_STRIDE + ka + 4]);
                ae[mt][0] = __float_as_uint(sXe[row * SA_STRIDE + ka]);
                ae[mt][1] = __float_as_uint(sXe[(row + 8) * SA_STRIDE + ka]);
                ae[mt][2] = __float_as_uint(sXe[row * SA_STRIDE + ka + 4]);
                ae[mt][3] = __float_as_uint(sXe[(row + 8) * SA_STRIDE + ka + 4]);
            }
            #pragma unroll
            for (int nt = 0; nt < 4; ++nt) {
                const int col = n0 + 8 * nt + g;
                const unsigned int br0 = __float_as_uint(sBr[(kk * 8 + c) * SB_STRIDE + col]);
                const unsigned int br1 = __float_as_uint(sBr[(kk * 8 + 4 + c) * SB_STRIDE + col]);
                const unsigned int be0 = __float_as_uint(sBe[(kk * 8 + c) * SB_STRIDE + col]);
                const unsigned int be1 = __float_as_uint(sBe[(kk * 8 + 4 + c) * SB_STRIDE + col]);
                #pragma unroll
                for (int mt = 0; mt < 2; ++mt) {
                    MMA_TF32(acc[mt][nt], ar[mt], br0, br1);
                    MMA_TF32(acc[mt][nt], ae[mt], br0, br1);
                    MMA_TF32(acc[mt][nt], ar[mt], be0, be1);
                }
            }
        }
    }

    // ---- epilogue: fields + diag + mask + store ----
    const unsigned int* em = mask + (size_t)(n * PP + p) * PP;
    #pragma unroll
    for (int mt = 0; mt < 2; ++mt) {
        #pragma unroll
        for (int nt = 0; nt < 4; ++nt) {
            const int u0e = n0 + 8 * nt + 2 * c;
            const float2 fp2 = *(const float2*)(sFp + u0e);
            const float2 fd2 = *(const float2*)(sFd + u0e);
            #pragma unroll
            for (int half = 0; half < 2; ++half) {
                const int q = m0 + 16 * mt + g + 8 * half;
                const float d0 = acc[mt][nt][2 * half + 0];
                const float d1 = acc[mt][nt][2 * half + 1];
                const float2 fq2 = *(const float2*)(g_Fq + ((size_t)(n * PP + q)) * UU + u0e);
                const float msk = (em[q] != 0u) ? 1.0f : 0.0f;
                const float de = (q == p) ? 1.0f : 0.0f;
                float2 o;
                o.x = (d0 + fq2.x + fp2.x + de * fd2.x) * msk;
                o.y = (d1 + fq2.y + fp2.y + de * fd2.y) * msk;
                *(float2*)(out + (((size_t)(n * PP + p)) * PP + q) * UU + u0e) = o;
            }
        }
    }
}

// ---------------- launch ----------------
extern "C" void kernel_launch(void* const* d_in, const int* in_sizes, int n_in,
                              void* d_out, int out_size) {
    (void)in_sizes; (void)n_in; (void)out_size;
    const float*        x      = (const float*)d_in[0];
    const unsigned int* mask   = (const unsigned int*)d_in[1];
    const float*        npart  = (const float*)d_in[2];
    const float*        alpha0 = (const float*)d_in[3];
    const float*        c00    = (const float*)d_in[4];
    const float*        c01    = (const float*)d_in[5];
    const float*        c10    = (const float*)d_in[6];
    const float*        c11    = (const float*)d_in[7];
    const float*        bias   = (const float*)d_in[8];
    const float*        dbias  = (const float*)d_in[9];
    float* out = (float*)d_out;

    fuse_kernel<<<dim3(NPG, NN), 256>>>(x, npart);
    pro_kernel<<<dim3(32, NN), 256>>>(npart, alpha0, c00, c01, c10, c11, bias, dbias);

    cudaFuncSetAttribute(main_kernel, cudaFuncAttributeMaxDynamicSharedMemorySize,
                         SMEM_FLOATS * 4);
    main_kernel<<<dim3(PP, NN), 256, SMEM_FLOATS * 4>>>(x, mask, c00, c01, c10, c11, out);
}